// round 1
// baseline (speedup 1.0000x reference)
#include <cuda_runtime.h>

// Problem constants
#define BATCH 8
#define CCH   256          // C_in == C_out
#define WID   4096
#define KW    7
#define PADW  3
#define WP    (WID + 2*PADW)   // 4102
#define WPA   4104             // padded row stride (multiple of 8 floats -> 32B aligned)
#define MROWS 768              // 3 * 256 stacked output rows (q,k,v)

// Scratch: qkv_pad[m][b][j], m in [0,768): 0..255 q, 256..511 k, 512..767 v
// j in [0,WP) on the padded width grid. ~101 MB static device allocation.
__device__ float g_qkv[(size_t)MROWS * BATCH * WPA];

// ---------------------------------------------------------------------------
// Kernel 1: fused q/k/v GEMM over the padded domain.
//   g_qkv[m][b][j] = sum_c Wsel[m%256][c] * xpad[b][c][j],  xpad[j] = x[j-3] (0 outside)
// Tiling: 128(M) x 128(N) x 16(K), 256 threads, 8x8 microtile per thread.
// ---------------------------------------------------------------------------
#define TM 128
#define TN 128
#define TK 16

__global__ __launch_bounds__(256, 2)
void qkv_gemm(const float* __restrict__ x,
              const float* __restrict__ wq,
              const float* __restrict__ wk,
              const float* __restrict__ wv)
{
    __shared__ float As[TK][TM + 1];  // [k][m], +1 pad kills STS bank conflicts
    __shared__ float Bs[TK][TN];      // [k][j]

    const int b  = blockIdx.z;
    const int mt = blockIdx.y;        // 0..5 : which 128-row slab of the 768 rows
    const int nt = blockIdx.x;        // 0..32
    const int m0 = (mt & 1) * 128;    // row offset within the selected weight
    const float* Wsel = (mt < 2) ? wq : (mt < 4) ? wk : wv;
    const int j0 = nt * TN;

    const int tid = threadIdx.x;
    const int ty = tid >> 4;          // 0..15
    const int tx = tid & 15;          // 0..15

    float acc[8][8];
    #pragma unroll
    for (int i = 0; i < 8; ++i)
        #pragma unroll
        for (int j = 0; j < 8; ++j) acc[i][j] = 0.f;

    const float* xb = x + (size_t)b * CCH * WID;

    for (int k0 = 0; k0 < CCH; k0 += TK) {
        // Load A tile: 128 rows x 16 k (weights). 2048 elems / 256 threads = 8.
        #pragma unroll
        for (int it = 0; it < 8; ++it) {
            int e   = tid + it * 256;
            int row = e >> 4;
            int kc  = e & 15;
            As[kc][row] = Wsel[(m0 + row) * CCH + (k0 + kc)];
        }
        // Load B tile: 16 k x 128 j (padded x). Coalesced in j; zero-fill pad.
        #pragma unroll
        for (int it = 0; it < 8; ++it) {
            int e   = tid + it * 256;
            int kk  = e >> 7;
            int jj  = e & 127;
            int col = j0 + jj - PADW;
            float v = 0.f;
            if (col >= 0 && col < WID)
                v = xb[(size_t)(k0 + kk) * WID + col];
            Bs[kk][jj] = v;
        }
        __syncthreads();

        #pragma unroll
        for (int kk = 0; kk < TK; ++kk) {
            float a[8], bb[8];
            #pragma unroll
            for (int i = 0; i < 8; ++i) a[i]  = As[kk][ty * 8 + i];
            #pragma unroll
            for (int j = 0; j < 8; ++j) bb[j] = Bs[kk][tx * 8 + j];
            #pragma unroll
            for (int i = 0; i < 8; ++i)
                #pragma unroll
                for (int j = 0; j < 8; ++j)
                    acc[i][j] = fmaf(a[i], bb[j], acc[i][j]);
        }
        __syncthreads();
    }

    // Store 8x8 microtile (vectorized fast path; scalar bounds-checked tail).
    const int col0 = j0 + tx * 8;
    #pragma unroll
    for (int i = 0; i < 8; ++i) {
        int m = mt * 128 + ty * 8 + i;   // global stacked row
        float* dst = g_qkv + ((size_t)m * BATCH + b) * WPA + col0;
        if (col0 + 8 <= WP) {
            float4 v0 = make_float4(acc[i][0], acc[i][1], acc[i][2], acc[i][3]);
            float4 v1 = make_float4(acc[i][4], acc[i][5], acc[i][6], acc[i][7]);
            reinterpret_cast<float4*>(dst)[0] = v0;
            reinterpret_cast<float4*>(dst)[1] = v1;
        } else {
            #pragma unroll
            for (int j = 0; j < 8; ++j)
                if (col0 + j < WP) dst[j] = acc[i][j];
        }
    }
}

// ---------------------------------------------------------------------------
// Kernel 2: per-element 7-tap windowed softmax attention.
//   out[b,o,w] = sum_i softmax_i(q[w] * k_pad[w+i]) * v_pad[w+i]
// q[w] on the padded grid is q_pad[w+3].
// ---------------------------------------------------------------------------
__global__ __launch_bounds__(256)
void attn_window(float* __restrict__ out)
{
    int idx = blockIdx.x * blockDim.x + threadIdx.x;
    const int total = BATCH * CCH * WID;
    if (idx >= total) return;

    int w = idx & (WID - 1);
    int t = idx >> 12;            // b*256 + o
    int o = t & (CCH - 1);
    int b = t >> 8;

    const float* Q = g_qkv + ((size_t)(      o) * BATCH + b) * WPA;
    const float* K = g_qkv + ((size_t)(256 + o) * BATCH + b) * WPA;
    const float* V = g_qkv + ((size_t)(512 + o) * BATCH + b) * WPA;

    float q = Q[w + PADW];

    float s[KW];
    float mmax = -1e30f;
    #pragma unroll
    for (int i = 0; i < KW; ++i) {
        s[i] = q * K[w + i];
        mmax = fmaxf(mmax, s[i]);
    }

    float sum = 0.f, accv = 0.f;
    #pragma unroll
    for (int i = 0; i < KW; ++i) {
        float e = __expf(s[i] - mmax);
        sum  += e;
        accv = fmaf(e, V[w + i], accv);
    }

    out[idx] = accv / sum;
}

// ---------------------------------------------------------------------------
extern "C" void kernel_launch(void* const* d_in, const int* in_sizes, int n_in,
                              void* d_out, int out_size)
{
    (void)in_sizes; (void)n_in; (void)out_size;
    const float* x  = (const float*)d_in[0];
    const float* wq = (const float*)d_in[1];
    const float* wk = (const float*)d_in[2];
    const float* wv = (const float*)d_in[3];
    float* out = (float*)d_out;

    dim3 grid((WP + TN - 1) / TN, MROWS / TM, BATCH);  // 33 x 6 x 8
    qkv_gemm<<<grid, 256>>>(x, wq, wk, wv);

    const int total = BATCH * CCH * WID;
    attn_window<<<total / 256, 256>>>(out);
}

// round 3
// speedup vs baseline: 2.5044x; 2.5044x over previous
#include <cuda_runtime.h>
#include <cuda_bf16.h>
#include <cstdint>

#define BATCH 8
#define CCH   256
#define WID   4096
#define GROUPS 3

// scratch: qkv[m][b][j], m = g*256 + o (g: 0=q,1=k,2=v), j in [0,4096)
__device__ float g_qkv[(size_t)GROUPS * CCH * BATCH * WID];

// ---------------------------------------------------------------------------
// helpers
// ---------------------------------------------------------------------------
__device__ __forceinline__ uint32_t sptr(const void* p) {
    return (uint32_t)__cvta_generic_to_shared(p);
}

__device__ __forceinline__ void split2(float f0, float f1, uint32_t& h, uint32_t& l) {
    __nv_bfloat16 h0 = __float2bfloat16(f0);
    __nv_bfloat16 h1 = __float2bfloat16(f1);
    __nv_bfloat16 l0 = __float2bfloat16(f0 - __bfloat162float(h0));
    __nv_bfloat16 l1 = __float2bfloat16(f1 - __bfloat162float(h1));
    h = (uint32_t)__bfloat16_as_ushort(h0) | ((uint32_t)__bfloat16_as_ushort(h1) << 16);
    l = (uint32_t)__bfloat16_as_ushort(l0) | ((uint32_t)__bfloat16_as_ushort(l1) << 16);
}

__device__ __forceinline__ void ldsm_x4(uint32_t addr, uint32_t& r0, uint32_t& r1,
                                        uint32_t& r2, uint32_t& r3) {
    asm volatile("ldmatrix.sync.aligned.m8n8.x4.shared.b16 {%0,%1,%2,%3}, [%4];"
                 : "=r"(r0), "=r"(r1), "=r"(r2), "=r"(r3) : "r"(addr));
}
__device__ __forceinline__ void ldsm_x4_t(uint32_t addr, uint32_t& r0, uint32_t& r1,
                                          uint32_t& r2, uint32_t& r3) {
    asm volatile("ldmatrix.sync.aligned.m8n8.x4.trans.shared.b16 {%0,%1,%2,%3}, [%4];"
                 : "=r"(r0), "=r"(r1), "=r"(r2), "=r"(r3) : "r"(addr));
}

__device__ __forceinline__ void mma16816(float* c, uint32_t a0, uint32_t a1,
                                         uint32_t a2, uint32_t a3,
                                         uint32_t b0, uint32_t b1) {
    asm volatile(
        "mma.sync.aligned.m16n8k16.row.col.f32.bf16.bf16.f32 "
        "{%0,%1,%2,%3}, {%4,%5,%6,%7}, {%8,%9}, {%0,%1,%2,%3};"
        : "+f"(c[0]), "+f"(c[1]), "+f"(c[2]), "+f"(c[3])
        : "r"(a0), "r"(a1), "r"(a2), "r"(a3), "r"(b0), "r"(b1));
}

// ---------------------------------------------------------------------------
// GEMM: qkv[g*256+o][b][j] = sum_c Wg[o][c] * x[b][c][j]
// CTA tile 128(m) x 128(n), k-chunk 32, bf16 hi/lo split (3 mma passes).
// ---------------------------------------------------------------------------
__global__ __launch_bounds__(256, 2)
void qkv_gemm_mma(const float* __restrict__ x,
                  const float* __restrict__ wq,
                  const float* __restrict__ wk,
                  const float* __restrict__ wv)
{
    // strides: A 40 bf16 = 80B (5x16B), B 136 bf16 = 272B (17x16B) -> LDSM conflict-free
    __shared__ __align__(16) __nv_bfloat16 Ah[128][40];
    __shared__ __align__(16) __nv_bfloat16 Al[128][40];
    __shared__ __align__(16) __nv_bfloat16 Bh[32][136];
    __shared__ __align__(16) __nv_bfloat16 Bl[32][136];

    const int nt = blockIdx.x;        // 0..31
    const int my = blockIdx.y;        // 0..5
    const int b  = blockIdx.z;        // 0..7
    const int g  = my >> 1;
    const int m0g = (my & 1) * 128;
    const int j0 = nt * 128;
    const float* Wg = (g == 0) ? wq : (g == 1) ? wk : wv;
    const float* xb = x + (size_t)b * CCH * WID;

    const int tid  = threadIdx.x;
    const int lane = tid & 31;
    const int wid  = tid >> 5;
    const int wm   = wid >> 2;        // 0..1
    const int wn   = wid & 3;         // 0..3

    float acc[4][4][4];
    #pragma unroll
    for (int i = 0; i < 4; ++i)
        #pragma unroll
        for (int j = 0; j < 4; ++j)
            #pragma unroll
            for (int r = 0; r < 4; ++r) acc[i][j][r] = 0.f;

    // ldmatrix per-thread source rows
    const int lt_tile = lane >> 3;    // 0..3
    const int lt_r    = lane & 7;

    #pragma unroll 1
    for (int kc = 0; kc < CCH; kc += 32) {
        // ---- load A tile: W[m0g..+127][kc..+31], 1024 float4, 4/thread ----
        #pragma unroll
        for (int i = 0; i < 4; ++i) {
            int e   = tid + i * 256;
            int row = e >> 3;
            int c4  = e & 7;
            float4 w4 = *(const float4*)(Wg + (size_t)(m0g + row) * CCH + kc + c4 * 4);
            uint32_t h01, l01, h23, l23;
            split2(w4.x, w4.y, h01, l01);
            split2(w4.z, w4.w, h23, l23);
            *(uint2*)&Ah[row][c4 * 4] = make_uint2(h01, h23);
            *(uint2*)&Al[row][c4 * 4] = make_uint2(l01, l23);
        }
        // ---- load B tile: x[kc..+31][j0..+127], 1024 float4, 4/thread ----
        #pragma unroll
        for (int i = 0; i < 4; ++i) {
            int e   = tid + i * 256;
            int row = e >> 5;
            int n4  = e & 31;
            float4 xv = *(const float4*)(xb + (size_t)(kc + row) * WID + j0 + n4 * 4);
            uint32_t h01, l01, h23, l23;
            split2(xv.x, xv.y, h01, l01);
            split2(xv.z, xv.w, h23, l23);
            *(uint2*)&Bh[row][n4 * 4] = make_uint2(h01, h23);
            *(uint2*)&Bl[row][n4 * 4] = make_uint2(l01, l23);
        }
        __syncthreads();

        #pragma unroll
        for (int ks = 0; ks < 2; ++ks) {
            const int kb = ks * 16;
            // A fragments: 4 m-atoms, hi & lo
            uint32_t ah[4][4], al[4][4];
            #pragma unroll
            for (int ma = 0; ma < 4; ++ma) {
                int row = wm * 64 + ma * 16 + (lt_tile & 1) * 8 + lt_r;
                int col = kb + (lt_tile >> 1) * 8;
                ldsm_x4(sptr(&Ah[row][col]), ah[ma][0], ah[ma][1], ah[ma][2], ah[ma][3]);
                ldsm_x4(sptr(&Al[row][col]), al[ma][0], al[ma][1], al[ma][2], al[ma][3]);
            }
            // B fragments: 4 n-atoms (2 x4.trans loads), hi & lo
            uint32_t bh[4][2], bl[4][2];
            #pragma unroll
            for (int np = 0; np < 2; ++np) {
                int krow = kb + (lt_tile & 1) * 8 + lt_r;
                int ncol = wn * 32 + np * 16 + (lt_tile >> 1) * 8;
                ldsm_x4_t(sptr(&Bh[krow][ncol]),
                          bh[np * 2][0], bh[np * 2][1], bh[np * 2 + 1][0], bh[np * 2 + 1][1]);
                ldsm_x4_t(sptr(&Bl[krow][ncol]),
                          bl[np * 2][0], bl[np * 2][1], bl[np * 2 + 1][0], bl[np * 2 + 1][1]);
            }
            // 3 split passes
            #pragma unroll
            for (int ma = 0; ma < 4; ++ma)
                #pragma unroll
                for (int na = 0; na < 4; ++na) {
                    mma16816(acc[ma][na], ah[ma][0], ah[ma][1], ah[ma][2], ah[ma][3],
                             bh[na][0], bh[na][1]);
                    mma16816(acc[ma][na], al[ma][0], al[ma][1], al[ma][2], al[ma][3],
                             bh[na][0], bh[na][1]);
                    mma16816(acc[ma][na], ah[ma][0], ah[ma][1], ah[ma][2], ah[ma][3],
                             bl[na][0], bl[na][1]);
                }
        }
        __syncthreads();
    }

    // ---- epilogue: write C tiles to scratch ----
    #pragma unroll
    for (int ma = 0; ma < 4; ++ma) {
        int r0 = m0g + wm * 64 + ma * 16 + (lane >> 2);
        #pragma unroll
        for (int na = 0; na < 4; ++na) {
            int jj = j0 + wn * 32 + na * 8 + (lane & 3) * 2;
            float* d0 = g_qkv + ((size_t)(g * 256 + r0) * BATCH + b) * WID + jj;
            float* d1 = d0 + (size_t)8 * BATCH * WID;   // row r0+8
            *(float2*)d0 = make_float2(acc[ma][na][0], acc[ma][na][1]);
            *(float2*)d1 = make_float2(acc[ma][na][2], acc[ma][na][3]);
        }
    }
}

// ---------------------------------------------------------------------------
// attention: 4 outputs/thread, zero taps outside [0,4096) (== conv of zero pad)
// ---------------------------------------------------------------------------
__global__ __launch_bounds__(256)
void attn_window4(float* __restrict__ out)
{
    int t4 = blockIdx.x * blockDim.x + threadIdx.x;
    int w  = (t4 & 1023) * 4;
    int t  = t4 >> 10;            // b*256 + o
    int o  = t & 255;
    int b  = t >> 8;

    const float* Q = g_qkv + ((size_t)o * BATCH + b) * WID;
    const float* K = Q + (size_t)256 * BATCH * WID;
    const float* V = Q + (size_t)512 * BATCH * WID;

    const float4 z4 = make_float4(0.f, 0.f, 0.f, 0.f);
    float4 q4 = *(const float4*)(Q + w);
    float4 km = (w >= 4)        ? *(const float4*)(K + w - 4) : z4;
    float4 kc = *(const float4*)(K + w);
    float4 kp = (w + 4 < WID)   ? *(const float4*)(K + w + 4) : z4;
    float4 vm = (w >= 4)        ? *(const float4*)(V + w - 4) : z4;
    float4 vc = *(const float4*)(V + w);
    float4 vp = (w + 4 < WID)   ? *(const float4*)(V + w + 4) : z4;

    float kk[10] = {km.y, km.z, km.w, kc.x, kc.y, kc.z, kc.w, kp.x, kp.y, kp.z};
    float vv[10] = {vm.y, vm.z, vm.w, vc.x, vc.y, vc.z, vc.w, vp.x, vp.y, vp.z};
    float qv[4]  = {q4.x, q4.y, q4.z, q4.w};

    float res[4];
    #pragma unroll
    for (int tt = 0; tt < 4; ++tt) {
        float s[7];
        float m = -1e30f;
        #pragma unroll
        for (int i = 0; i < 7; ++i) {
            s[i] = qv[tt] * kk[tt + i];
            m = fmaxf(m, s[i]);
        }
        float sum = 0.f, accn = 0.f;
        #pragma unroll
        for (int i = 0; i < 7; ++i) {
            float e = __expf(s[i] - m);
            sum += e;
            accn = fmaf(e, vv[tt + i], accn);
        }
        res[tt] = accn / sum;
    }
    *(float4*)(out + (size_t)t * WID + w) = make_float4(res[0], res[1], res[2], res[3]);
}

// ---------------------------------------------------------------------------
extern "C" void kernel_launch(void* const* d_in, const int* in_sizes, int n_in,
                              void* d_out, int out_size)
{
    (void)in_sizes; (void)n_in; (void)out_size;
    const float* x  = (const float*)d_in[0];
    const float* wq = (const float*)d_in[1];
    const float* wk = (const float*)d_in[2];
    const float* wv = (const float*)d_in[3];
    float* out = (float*)d_out;

    dim3 grid(32, 6, 8);
    qkv_gemm_mma<<<grid, 256>>>(x, wq, wk, wv);

    attn_window4<<<(BATCH * CCH * WID) / (256 * 4), 256>>>(out);
}

// round 4
// speedup vs baseline: 2.5386x; 1.0137x over previous
#include <cuda_runtime.h>
#include <cuda_bf16.h>
#include <cstdint>

#define BATCH 8
#define CCH   256
#define WID   4096
#define GROUPS 3

// fp32 scratch: qkv[g*256+o][b][j]
__device__ float g_qkv[(size_t)GROUPS * CCH * BATCH * WID];
// pre-split bf16 operands
__device__ __nv_bfloat16 g_xh[(size_t)BATCH * CCH * WID];
__device__ __nv_bfloat16 g_xl[(size_t)BATCH * CCH * WID];
__device__ __nv_bfloat16 g_wh[(size_t)GROUPS * CCH * CCH];
__device__ __nv_bfloat16 g_wl[(size_t)GROUPS * CCH * CCH];

// ---------------------------------------------------------------------------
__device__ __forceinline__ uint32_t sptr(const void* p) {
    return (uint32_t)__cvta_generic_to_shared(p);
}
__device__ __forceinline__ void split2(float f0, float f1, uint32_t& h, uint32_t& l) {
    __nv_bfloat16 h0 = __float2bfloat16(f0);
    __nv_bfloat16 h1 = __float2bfloat16(f1);
    __nv_bfloat16 l0 = __float2bfloat16(f0 - __bfloat162float(h0));
    __nv_bfloat16 l1 = __float2bfloat16(f1 - __bfloat162float(h1));
    h = (uint32_t)__bfloat16_as_ushort(h0) | ((uint32_t)__bfloat16_as_ushort(h1) << 16);
    l = (uint32_t)__bfloat16_as_ushort(l0) | ((uint32_t)__bfloat16_as_ushort(l1) << 16);
}
__device__ __forceinline__ void ldsm_x4(uint32_t addr, uint32_t& r0, uint32_t& r1,
                                        uint32_t& r2, uint32_t& r3) {
    asm volatile("ldmatrix.sync.aligned.m8n8.x4.shared.b16 {%0,%1,%2,%3}, [%4];"
                 : "=r"(r0), "=r"(r1), "=r"(r2), "=r"(r3) : "r"(addr));
}
__device__ __forceinline__ void ldsm_x4_t(uint32_t addr, uint32_t& r0, uint32_t& r1,
                                          uint32_t& r2, uint32_t& r3) {
    asm volatile("ldmatrix.sync.aligned.m8n8.x4.trans.shared.b16 {%0,%1,%2,%3}, [%4];"
                 : "=r"(r0), "=r"(r1), "=r"(r2), "=r"(r3) : "r"(addr));
}
__device__ __forceinline__ void mma16816(float* c, uint32_t a0, uint32_t a1,
                                         uint32_t a2, uint32_t a3,
                                         uint32_t b0, uint32_t b1) {
    asm volatile(
        "mma.sync.aligned.m16n8k16.row.col.f32.bf16.bf16.f32 "
        "{%0,%1,%2,%3}, {%4,%5,%6,%7}, {%8,%9}, {%0,%1,%2,%3};"
        : "+f"(c[0]), "+f"(c[1]), "+f"(c[2]), "+f"(c[3])
        : "r"(a0), "r"(a1), "r"(a2), "r"(a3), "r"(b0), "r"(b1));
}
#define CP16(dst, src) \
    asm volatile("cp.async.cg.shared.global [%0], [%1], 16;" :: "r"(dst), "l"(src))
#define CP_COMMIT() asm volatile("cp.async.commit_group;")
#define CP_WAIT(n)  asm volatile("cp.async.wait_group %0;" :: "n"(n))

// ---------------------------------------------------------------------------
// Kernel 0: split fp32 -> bf16 hi/lo (x and the three weights)
// ---------------------------------------------------------------------------
#define NX4 (BATCH * CCH * WID / 4)   // 2097152
#define NW4 (CCH * CCH / 4)           // 16384

__global__ __launch_bounds__(256)
void convert_split(const float* __restrict__ x, const float* __restrict__ wq,
                   const float* __restrict__ wk, const float* __restrict__ wv)
{
    int idx = blockIdx.x * 256 + threadIdx.x;
    if (idx < NX4) {
        float4 v = ((const float4*)x)[idx];
        uint32_t h01, l01, h23, l23;
        split2(v.x, v.y, h01, l01);
        split2(v.z, v.w, h23, l23);
        ((uint2*)g_xh)[idx] = make_uint2(h01, h23);
        ((uint2*)g_xl)[idx] = make_uint2(l01, l23);
    } else {
        int r = idx - NX4;
        if (r < 3 * NW4) {
            int g = r / NW4, e = r % NW4;
            const float* W = (g == 0) ? wq : (g == 1) ? wk : wv;
            float4 v = ((const float4*)W)[e];
            uint32_t h01, l01, h23, l23;
            split2(v.x, v.y, h01, l01);
            split2(v.z, v.w, h23, l23);
            ((uint2*)g_wh)[g * NW4 + e] = make_uint2(h01, h23);
            ((uint2*)g_wl)[g * NW4 + e] = make_uint2(l01, l23);
        }
    }
}

// ---------------------------------------------------------------------------
// Kernel 1: GEMM with pre-split bf16, cp.async double-buffered.
// CTA 128m x 128n, k-chunk 32, 3 mma passes (ah*bh + al*bh + ah*bl).
// SMEM (dynamic, bytes):
//   A buf s: s*20480      : Ah[128][40], Al at +10240
//   B buf s: 40960+s*17408: Bh[32][136], Bl at +8704
// ---------------------------------------------------------------------------
#define SMEM_GEMM 75776

__device__ __forceinline__ void prefetch_chunk(
    char* s, int buf, int tid,
    const __nv_bfloat16* __restrict__ whg, const __nv_bfloat16* __restrict__ wlg,
    const __nv_bfloat16* __restrict__ xhb, const __nv_bfloat16* __restrict__ xlb,
    int kc, int j0)
{
    uint32_t a_h = sptr(s + buf * 20480);
    uint32_t a_l = a_h + 10240;
    uint32_t b_h = sptr(s + 40960 + buf * 17408);
    uint32_t b_l = b_h + 8704;
    #pragma unroll
    for (int i = 0; i < 2; ++i) {
        int e = tid + i * 256;
        int row = e >> 2, seg = e & 3;
        uint32_t off = (uint32_t)(row * 40 + seg * 8) * 2;
        const __nv_bfloat16* sh = whg + (size_t)row * CCH + kc + seg * 8;
        const __nv_bfloat16* sl = wlg + (size_t)row * CCH + kc + seg * 8;
        CP16(a_h + off, sh);
        CP16(a_l + off, sl);
    }
    #pragma unroll
    for (int i = 0; i < 2; ++i) {
        int e = tid + i * 256;
        int row = e >> 4, seg = e & 15;
        uint32_t off = (uint32_t)(row * 136 + seg * 8) * 2;
        const __nv_bfloat16* sh = xhb + (size_t)(kc + row) * WID + j0 + seg * 8;
        const __nv_bfloat16* sl = xlb + (size_t)(kc + row) * WID + j0 + seg * 8;
        CP16(b_h + off, sh);
        CP16(b_l + off, sl);
    }
}

__global__ __launch_bounds__(256, 2)
void qkv_gemm_mma()
{
    extern __shared__ char smem[];

    const int nt = blockIdx.x;        // 0..31
    const int my = blockIdx.y;        // 0..5
    const int b  = blockIdx.z;        // 0..7
    const int g  = my >> 1;
    const int m0g = (my & 1) * 128;
    const int j0 = nt * 128;

    const __nv_bfloat16* whg = g_wh + (size_t)g * CCH * CCH + (size_t)m0g * CCH;
    const __nv_bfloat16* wlg = g_wl + (size_t)g * CCH * CCH + (size_t)m0g * CCH;
    const __nv_bfloat16* xhb = g_xh + (size_t)b * CCH * WID;
    const __nv_bfloat16* xlb = g_xl + (size_t)b * CCH * WID;

    const int tid  = threadIdx.x;
    const int lane = tid & 31;
    const int wid  = tid >> 5;
    const int wm   = wid >> 2;        // 0..1
    const int wn   = wid & 3;         // 0..3
    const int lt_tile = lane >> 3;
    const int lt_r    = lane & 7;

    float acc[4][4][4];
    #pragma unroll
    for (int i = 0; i < 4; ++i)
        #pragma unroll
        for (int j = 0; j < 4; ++j)
            #pragma unroll
            for (int r = 0; r < 4; ++r) acc[i][j][r] = 0.f;

    prefetch_chunk(smem, 0, tid, whg, wlg, xhb, xlb, 0, j0);
    CP_COMMIT();

    #pragma unroll 1
    for (int kc8 = 0; kc8 < 8; ++kc8) {
        const int buf = kc8 & 1;
        if (kc8 < 7) {
            prefetch_chunk(smem, buf ^ 1, tid, whg, wlg, xhb, xlb, (kc8 + 1) * 32, j0);
            CP_COMMIT();
            CP_WAIT(1);
        } else {
            CP_WAIT(0);
        }
        __syncthreads();

        const __nv_bfloat16* Ahp = (const __nv_bfloat16*)(smem + buf * 20480);
        const __nv_bfloat16* Alp = (const __nv_bfloat16*)(smem + buf * 20480 + 10240);
        const __nv_bfloat16* Bhp = (const __nv_bfloat16*)(smem + 40960 + buf * 17408);
        const __nv_bfloat16* Blp = (const __nv_bfloat16*)(smem + 40960 + buf * 17408 + 8704);

        #pragma unroll
        for (int ks = 0; ks < 2; ++ks) {
            const int kb = ks * 16;
            // B fragments (4 n-atoms, hi & lo)
            uint32_t bh[4][2], bl[4][2];
            #pragma unroll
            for (int np = 0; np < 2; ++np) {
                int krow = kb + (lt_tile & 1) * 8 + lt_r;
                int ncol = wn * 32 + np * 16 + (lt_tile >> 1) * 8;
                ldsm_x4_t(sptr(Bhp + krow * 136 + ncol),
                          bh[np * 2][0], bh[np * 2][1], bh[np * 2 + 1][0], bh[np * 2 + 1][1]);
                ldsm_x4_t(sptr(Blp + krow * 136 + ncol),
                          bl[np * 2][0], bl[np * 2][1], bl[np * 2 + 1][0], bl[np * 2 + 1][1]);
            }
            // A fragments per m-atom, then 3 split passes
            #pragma unroll
            for (int ma = 0; ma < 4; ++ma) {
                int row = wm * 64 + ma * 16 + (lt_tile & 1) * 8 + lt_r;
                int col = kb + (lt_tile >> 1) * 8;
                uint32_t ah[4], al[4];
                ldsm_x4(sptr(Ahp + row * 40 + col), ah[0], ah[1], ah[2], ah[3]);
                ldsm_x4(sptr(Alp + row * 40 + col), al[0], al[1], al[2], al[3]);
                #pragma unroll
                for (int na = 0; na < 4; ++na) {
                    mma16816(acc[ma][na], ah[0], ah[1], ah[2], ah[3], bh[na][0], bh[na][1]);
                    mma16816(acc[ma][na], al[0], al[1], al[2], al[3], bh[na][0], bh[na][1]);
                    mma16816(acc[ma][na], ah[0], ah[1], ah[2], ah[3], bl[na][0], bl[na][1]);
                }
            }
        }
        __syncthreads();
    }

    // epilogue
    #pragma unroll
    for (int ma = 0; ma < 4; ++ma) {
        int r0 = m0g + wm * 64 + ma * 16 + (lane >> 2);
        #pragma unroll
        for (int na = 0; na < 4; ++na) {
            int jj = j0 + wn * 32 + na * 8 + (lane & 3) * 2;
            float* d0 = g_qkv + ((size_t)(g * 256 + r0) * BATCH + b) * WID + jj;
            float* d1 = d0 + (size_t)8 * BATCH * WID;
            *(float2*)d0 = make_float2(acc[ma][na][0], acc[ma][na][1]);
            *(float2*)d1 = make_float2(acc[ma][na][2], acc[ma][na][3]);
        }
    }
}

// ---------------------------------------------------------------------------
// Kernel 2: windowed softmax, 8 outputs/thread
// ---------------------------------------------------------------------------
__global__ __launch_bounds__(256)
void attn_window8(float* __restrict__ out)
{
    int t8 = blockIdx.x * 256 + threadIdx.x;
    int w  = (t8 & 511) * 8;
    int t  = t8 >> 9;             // b*256 + o
    int o  = t & 255;
    int b  = t >> 8;

    const float* Q = g_qkv + ((size_t)o * BATCH + b) * WID;
    const float* K = Q + (size_t)256 * BATCH * WID;
    const float* V = Q + (size_t)512 * BATCH * WID;

    const float4 z4 = make_float4(0.f, 0.f, 0.f, 0.f);
    float4 q0 = *(const float4*)(Q + w);
    float4 q1 = *(const float4*)(Q + w + 4);
    float4 km = (w >= 4)        ? *(const float4*)(K + w - 4) : z4;
    float4 k0 = *(const float4*)(K + w);
    float4 k1 = *(const float4*)(K + w + 4);
    float4 kp = (w + 8 < WID)   ? *(const float4*)(K + w + 8) : z4;
    float4 vm = (w >= 4)        ? *(const float4*)(V + w - 4) : z4;
    float4 v0 = *(const float4*)(V + w);
    float4 v1 = *(const float4*)(V + w + 4);
    float4 vp = (w + 8 < WID)   ? *(const float4*)(V + w + 8) : z4;

    float kk[14] = {km.y, km.z, km.w, k0.x, k0.y, k0.z, k0.w,
                    k1.x, k1.y, k1.z, k1.w, kp.x, kp.y, kp.z};
    float vv[14] = {vm.y, vm.z, vm.w, v0.x, v0.y, v0.z, v0.w,
                    v1.x, v1.y, v1.z, v1.w, vp.x, vp.y, vp.z};
    float qv[8]  = {q0.x, q0.y, q0.z, q0.w, q1.x, q1.y, q1.z, q1.w};

    float res[8];
    #pragma unroll
    for (int tt = 0; tt < 8; ++tt) {
        float s[7];
        float m = -1e30f;
        #pragma unroll
        for (int i = 0; i < 7; ++i) {
            s[i] = qv[tt] * kk[tt + i];
            m = fmaxf(m, s[i]);
        }
        float sum = 0.f, accn = 0.f;
        #pragma unroll
        for (int i = 0; i < 7; ++i) {
            float e = __expf(s[i] - m);
            sum += e;
            accn = fmaf(e, vv[tt + i], accn);
        }
        res[tt] = accn / sum;
    }
    float* dst = out + (size_t)t * WID + w;
    *(float4*)dst       = make_float4(res[0], res[1], res[2], res[3]);
    *(float4*)(dst + 4) = make_float4(res[4], res[5], res[6], res[7]);
}

// ---------------------------------------------------------------------------
extern "C" void kernel_launch(void* const* d_in, const int* in_sizes, int n_in,
                              void* d_out, int out_size)
{
    (void)in_sizes; (void)n_in; (void)out_size;
    const float* x  = (const float*)d_in[0];
    const float* wq = (const float*)d_in[1];
    const float* wk = (const float*)d_in[2];
    const float* wv = (const float*)d_in[3];
    float* out = (float*)d_out;

    cudaFuncSetAttribute(qkv_gemm_mma, cudaFuncAttributeMaxDynamicSharedMemorySize, SMEM_GEMM);

    convert_split<<<(NX4 + 3 * NW4 + 255) / 256, 256>>>(x, wq, wk, wv);

    dim3 grid(32, 6, 8);
    qkv_gemm_mma<<<grid, 256, SMEM_GEMM>>>();

    attn_window8<<<(BATCH * CCH * WID) / (256 * 8), 256>>>(out);
}

// round 5
// speedup vs baseline: 2.5743x; 1.0141x over previous
#include <cuda_runtime.h>
#include <cuda_bf16.h>
#include <cstdint>

#define BATCH 8
#define CCH   256
#define WID   4096
#define GROUPS 3

// fp32 scratch: qkv[g*256+o][b][j]
__device__ float g_qkv[(size_t)GROUPS * CCH * BATCH * WID];
// pre-split bf16 operands
__device__ __nv_bfloat16 g_xh[(size_t)BATCH * CCH * WID];
__device__ __nv_bfloat16 g_xl[(size_t)BATCH * CCH * WID];
__device__ __nv_bfloat16 g_wh[(size_t)GROUPS * CCH * CCH];
__device__ __nv_bfloat16 g_wl[(size_t)GROUPS * CCH * CCH];

// ---------------------------------------------------------------------------
__device__ __forceinline__ uint32_t sptr(const void* p) {
    return (uint32_t)__cvta_generic_to_shared(p);
}
__device__ __forceinline__ void split2(float f0, float f1, uint32_t& h, uint32_t& l) {
    __nv_bfloat16 h0 = __float2bfloat16(f0);
    __nv_bfloat16 h1 = __float2bfloat16(f1);
    __nv_bfloat16 l0 = __float2bfloat16(f0 - __bfloat162float(h0));
    __nv_bfloat16 l1 = __float2bfloat16(f1 - __bfloat162float(h1));
    h = (uint32_t)__bfloat16_as_ushort(h0) | ((uint32_t)__bfloat16_as_ushort(h1) << 16);
    l = (uint32_t)__bfloat16_as_ushort(l0) | ((uint32_t)__bfloat16_as_ushort(l1) << 16);
}
__device__ __forceinline__ void ldsm_x4(uint32_t addr, uint32_t& r0, uint32_t& r1,
                                        uint32_t& r2, uint32_t& r3) {
    asm volatile("ldmatrix.sync.aligned.m8n8.x4.shared.b16 {%0,%1,%2,%3}, [%4];"
                 : "=r"(r0), "=r"(r1), "=r"(r2), "=r"(r3) : "r"(addr));
}
__device__ __forceinline__ void ldsm_x4_t(uint32_t addr, uint32_t& r0, uint32_t& r1,
                                          uint32_t& r2, uint32_t& r3) {
    asm volatile("ldmatrix.sync.aligned.m8n8.x4.trans.shared.b16 {%0,%1,%2,%3}, [%4];"
                 : "=r"(r0), "=r"(r1), "=r"(r2), "=r"(r3) : "r"(addr));
}
__device__ __forceinline__ void mma16816(float* c, const uint32_t* a,
                                         uint32_t b0, uint32_t b1) {
    asm volatile(
        "mma.sync.aligned.m16n8k16.row.col.f32.bf16.bf16.f32 "
        "{%0,%1,%2,%3}, {%4,%5,%6,%7}, {%8,%9}, {%0,%1,%2,%3};"
        : "+f"(c[0]), "+f"(c[1]), "+f"(c[2]), "+f"(c[3])
        : "r"(a[0]), "r"(a[1]), "r"(a[2]), "r"(a[3]), "r"(b0), "r"(b1));
}
#define CP16(dst, src) \
    asm volatile("cp.async.cg.shared.global [%0], [%1], 16;" :: "r"(dst), "l"(src))
#define CP_COMMIT() asm volatile("cp.async.commit_group;")
#define CP_WAIT(n)  asm volatile("cp.async.wait_group %0;" :: "n"(n))

// ---------------------------------------------------------------------------
// Kernel 0: split fp32 -> bf16 hi/lo
// ---------------------------------------------------------------------------
#define NX4 (BATCH * CCH * WID / 4)   // 2097152
#define NW4 (CCH * CCH / 4)           // 16384

__global__ __launch_bounds__(256)
void convert_split(const float* __restrict__ x, const float* __restrict__ wq,
                   const float* __restrict__ wk, const float* __restrict__ wv)
{
    int idx = blockIdx.x * 256 + threadIdx.x;
    if (idx < NX4) {
        float4 v = ((const float4*)x)[idx];
        uint32_t h01, l01, h23, l23;
        split2(v.x, v.y, h01, l01);
        split2(v.z, v.w, h23, l23);
        ((uint2*)g_xh)[idx] = make_uint2(h01, h23);
        ((uint2*)g_xl)[idx] = make_uint2(l01, l23);
    } else {
        int r = idx - NX4;
        if (r < 3 * NW4) {
            int g = r / NW4, e = r % NW4;
            const float* W = (g == 0) ? wq : (g == 1) ? wk : wv;
            float4 v = ((const float4*)W)[e];
            uint32_t h01, l01, h23, l23;
            split2(v.x, v.y, h01, l01);
            split2(v.z, v.w, h23, l23);
            ((uint2*)g_wh)[g * NW4 + e] = make_uint2(h01, h23);
            ((uint2*)g_wl)[g * NW4 + e] = make_uint2(l01, l23);
        }
    }
}

// ---------------------------------------------------------------------------
// Kernel 1: GEMM, pre-split bf16, 3-stage cp.async, pass-major MMA order.
// Stage layout (per stage, 37888 B): Ah[128][40] @0, Al @10240,
//                                    Bh[32][136] @20480, Bl @29184
// ---------------------------------------------------------------------------
#define STAGE_BYTES 37888
#define SMEM_GEMM   (3 * STAGE_BYTES)   // 113664

__device__ __forceinline__ void prefetch_chunk(
    char* s, int stage, int tid,
    const __nv_bfloat16* __restrict__ whg, const __nv_bfloat16* __restrict__ wlg,
    const __nv_bfloat16* __restrict__ xhb, const __nv_bfloat16* __restrict__ xlb,
    int kc, int j0)
{
    uint32_t base = sptr(s + stage * STAGE_BYTES);
    uint32_t a_h = base;
    uint32_t a_l = base + 10240;
    uint32_t b_h = base + 20480;
    uint32_t b_l = base + 29184;
    #pragma unroll
    for (int i = 0; i < 2; ++i) {
        int e = tid + i * 256;
        int row = e >> 2, seg = e & 3;
        uint32_t off = (uint32_t)(row * 40 + seg * 8) * 2;
        CP16(a_h + off, whg + (size_t)row * CCH + kc + seg * 8);
        CP16(a_l + off, wlg + (size_t)row * CCH + kc + seg * 8);
    }
    #pragma unroll
    for (int i = 0; i < 2; ++i) {
        int e = tid + i * 256;
        int row = e >> 4, seg = e & 15;
        uint32_t off = (uint32_t)(row * 136 + seg * 8) * 2;
        CP16(b_h + off, xhb + (size_t)(kc + row) * WID + j0 + seg * 8);
        CP16(b_l + off, xlb + (size_t)(kc + row) * WID + j0 + seg * 8);
    }
}

__global__ __launch_bounds__(256, 2)
void qkv_gemm_mma()
{
    extern __shared__ char smem[];

    const int nt = blockIdx.x;
    const int my = blockIdx.y;
    const int b  = blockIdx.z;
    const int g  = my >> 1;
    const int m0g = (my & 1) * 128;
    const int j0 = nt * 128;

    const __nv_bfloat16* whg = g_wh + (size_t)g * CCH * CCH + (size_t)m0g * CCH;
    const __nv_bfloat16* wlg = g_wl + (size_t)g * CCH * CCH + (size_t)m0g * CCH;
    const __nv_bfloat16* xhb = g_xh + (size_t)b * CCH * WID;
    const __nv_bfloat16* xlb = g_xl + (size_t)b * CCH * WID;

    const int tid  = threadIdx.x;
    const int lane = tid & 31;
    const int wid  = tid >> 5;
    const int wm   = wid >> 2;
    const int wn   = wid & 3;
    const int lt_tile = lane >> 3;
    const int lt_r    = lane & 7;

    float acc[4][4][4];
    #pragma unroll
    for (int i = 0; i < 4; ++i)
        #pragma unroll
        for (int j = 0; j < 4; ++j)
            #pragma unroll
            for (int r = 0; r < 4; ++r) acc[i][j][r] = 0.f;

    prefetch_chunk(smem, 0, tid, whg, wlg, xhb, xlb, 0, j0);
    CP_COMMIT();
    prefetch_chunk(smem, 1, tid, whg, wlg, xhb, xlb, 32, j0);
    CP_COMMIT();

    #pragma unroll 1
    for (int kc8 = 0; kc8 < 8; ++kc8) {
        const int stage = kc8 % 3;
        if (kc8 < 7) { CP_WAIT(1); } else { CP_WAIT(0); }
        __syncthreads();

        const char* sbuf = smem + stage * STAGE_BYTES;
        const __nv_bfloat16* Ahp = (const __nv_bfloat16*)(sbuf);
        const __nv_bfloat16* Alp = (const __nv_bfloat16*)(sbuf + 10240);
        const __nv_bfloat16* Bhp = (const __nv_bfloat16*)(sbuf + 20480);
        const __nv_bfloat16* Blp = (const __nv_bfloat16*)(sbuf + 29184);

        #pragma unroll
        for (int ks = 0; ks < 2; ++ks) {
            const int kb = ks * 16;
            uint32_t bh[4][2], bl[4][2];
            #pragma unroll
            for (int np = 0; np < 2; ++np) {
                int krow = kb + (lt_tile & 1) * 8 + lt_r;
                int ncol = wn * 32 + np * 16 + (lt_tile >> 1) * 8;
                ldsm_x4_t(sptr(Bhp + krow * 136 + ncol),
                          bh[np * 2][0], bh[np * 2][1], bh[np * 2 + 1][0], bh[np * 2 + 1][1]);
                ldsm_x4_t(sptr(Blp + krow * 136 + ncol),
                          bl[np * 2][0], bl[np * 2][1], bl[np * 2 + 1][0], bl[np * 2 + 1][1]);
            }
            uint32_t ah[4][4], al[4][4];
            #pragma unroll
            for (int ma = 0; ma < 4; ++ma) {
                int row = wm * 64 + ma * 16 + (lt_tile & 1) * 8 + lt_r;
                int col = kb + (lt_tile >> 1) * 8;
                ldsm_x4(sptr(Ahp + row * 40 + col), ah[ma][0], ah[ma][1], ah[ma][2], ah[ma][3]);
                ldsm_x4(sptr(Alp + row * 40 + col), al[ma][0], al[ma][1], al[ma][2], al[ma][3]);
            }
            // pass-major: 16 independent HMMAs between same-acc reuse
            #pragma unroll
            for (int ma = 0; ma < 4; ++ma)
                #pragma unroll
                for (int na = 0; na < 4; ++na)
                    mma16816(acc[ma][na], ah[ma], bh[na][0], bh[na][1]);
            #pragma unroll
            for (int ma = 0; ma < 4; ++ma)
                #pragma unroll
                for (int na = 0; na < 4; ++na)
                    mma16816(acc[ma][na], al[ma], bh[na][0], bh[na][1]);
            #pragma unroll
            for (int ma = 0; ma < 4; ++ma)
                #pragma unroll
                for (int na = 0; na < 4; ++na)
                    mma16816(acc[ma][na], ah[ma], bl[na][0], bl[na][1]);
        }
        __syncthreads();

        if (kc8 < 6) {
            prefetch_chunk(smem, (kc8 + 2) % 3, tid, whg, wlg, xhb, xlb, (kc8 + 2) * 32, j0);
            CP_COMMIT();
        }
    }

    // epilogue
    #pragma unroll
    for (int ma = 0; ma < 4; ++ma) {
        int r0 = m0g + wm * 64 + ma * 16 + (lane >> 2);
        #pragma unroll
        for (int na = 0; na < 4; ++na) {
            int jj = j0 + wn * 32 + na * 8 + (lane & 3) * 2;
            float* d0 = g_qkv + ((size_t)(g * 256 + r0) * BATCH + b) * WID + jj;
            float* d1 = d0 + (size_t)8 * BATCH * WID;
            *(float2*)d0 = make_float2(acc[ma][na][0], acc[ma][na][1]);
            *(float2*)d1 = make_float2(acc[ma][na][2], acc[ma][na][3]);
        }
    }
}

// ---------------------------------------------------------------------------
// Kernel 2: windowed softmax, 8 outputs/thread
// ---------------------------------------------------------------------------
__global__ __launch_bounds__(256)
void attn_window8(float* __restrict__ out)
{
    int t8 = blockIdx.x * 256 + threadIdx.x;
    int w  = (t8 & 511) * 8;
    int t  = t8 >> 9;
    int o  = t & 255;
    int b  = t >> 8;

    const float* Q = g_qkv + ((size_t)o * BATCH + b) * WID;
    const float* K = Q + (size_t)256 * BATCH * WID;
    const float* V = Q + (size_t)512 * BATCH * WID;

    const float4 z4 = make_float4(0.f, 0.f, 0.f, 0.f);
    float4 q0 = *(const float4*)(Q + w);
    float4 q1 = *(const float4*)(Q + w + 4);
    float4 km = (w >= 4)      ? *(const float4*)(K + w - 4) : z4;
    float4 k0 = *(const float4*)(K + w);
    float4 k1 = *(const float4*)(K + w + 4);
    float4 kp = (w + 8 < WID) ? *(const float4*)(K + w + 8) : z4;
    float4 vm = (w >= 4)      ? *(const float4*)(V + w - 4) : z4;
    float4 v0 = *(const float4*)(V + w);
    float4 v1 = *(const float4*)(V + w + 4);
    float4 vp = (w + 8 < WID) ? *(const float4*)(V + w + 8) : z4;

    float kk[14] = {km.y, km.z, km.w, k0.x, k0.y, k0.z, k0.w,
                    k1.x, k1.y, k1.z, k1.w, kp.x, kp.y, kp.z};
    float vv[14] = {vm.y, vm.z, vm.w, v0.x, v0.y, v0.z, v0.w,
                    v1.x, v1.y, v1.z, v1.w, vp.x, vp.y, vp.z};
    float qv[8]  = {q0.x, q0.y, q0.z, q0.w, q1.x, q1.y, q1.z, q1.w};

    float res[8];
    #pragma unroll
    for (int tt = 0; tt < 8; ++tt) {
        float s[7];
        float m = -1e30f;
        #pragma unroll
        for (int i = 0; i < 7; ++i) {
            s[i] = qv[tt] * kk[tt + i];
            m = fmaxf(m, s[i]);
        }
        float sum = 0.f, accn = 0.f;
        #pragma unroll
        for (int i = 0; i < 7; ++i) {
            float e = __expf(s[i] - m);
            sum += e;
            accn = fmaf(e, vv[tt + i], accn);
        }
        res[tt] = accn / sum;
    }
    float* dst = out + (size_t)t * WID + w;
    *(float4*)dst       = make_float4(res[0], res[1], res[2], res[3]);
    *(float4*)(dst + 4) = make_float4(res[4], res[5], res[6], res[7]);
}

// ---------------------------------------------------------------------------
extern "C" void kernel_launch(void* const* d_in, const int* in_sizes, int n_in,
                              void* d_out, int out_size)
{
    (void)in_sizes; (void)n_in; (void)out_size;
    const float* x  = (const float*)d_in[0];
    const float* wq = (const float*)d_in[1];
    const float* wk = (const float*)d_in[2];
    const float* wv = (const float*)d_in[3];
    float* out = (float*)d_out;

    cudaFuncSetAttribute(qkv_gemm_mma, cudaFuncAttributeMaxDynamicSharedMemorySize, SMEM_GEMM);

    convert_split<<<(NX4 + 3 * NW4 + 255) / 256, 256>>>(x, wq, wk, wv);

    dim3 grid(32, 6, 8);
    qkv_gemm_mma<<<grid, 256, SMEM_GEMM>>>();

    attn_window8<<<(BATCH * CCH * WID) / (256 * 8), 256>>>(out);
}